// round 7
// baseline (speedup 1.0000x reference)
#include <cuda_runtime.h>
#include <cstdint>

#define F0 339
#define F1 5825
#define F2 64
#define NROWS 6228
#define RK 128
#define CH 256

__device__ float g_Q[NROWS * CH];
__device__ float g_W1t[CH * CH];   // wfc1 preconverted to rna-tf32 bits

// ============================ helpers ============================
__device__ __forceinline__ uint32_t smem_u32(const void* p) {
    uint32_t a;
    asm("{ .reg .u64 t; cvta.to.shared.u64 t, %1; cvt.u32.u64 %0, t; }" : "=r"(a) : "l"(p));
    return a;
}
__device__ __forceinline__ uint32_t f2tf32(float x) {
    uint32_t u;
    asm("cvt.rna.tf32.f32 %0, %1;" : "=r"(u) : "f"(x));
    return u;
}
#define MMA_TF32(d, a, b) \
    asm volatile("mma.sync.aligned.m16n8k8.row.col.f32.tf32.tf32.f32 " \
        "{%0,%1,%2,%3}, {%4,%5,%6,%7}, {%8,%9}, {%0,%1,%2,%3};" \
        : "+f"((d)[0]), "+f"((d)[1]), "+f"((d)[2]), "+f"((d)[3]) \
        : "r"((a)[0]), "r"((a)[1]), "r"((a)[2]), "r"((a)[3]), \
          "r"((b)[0]), "r"((b)[1]))
#define CP_ASYNC16(dst, src) \
    asm volatile("cp.async.cg.shared.global [%0], [%1], 16;" :: "r"(dst), "l"(src))
#define CP_COMMIT() asm volatile("cp.async.commit_group;" ::: "memory")
#define CP_WAIT(n)  asm volatile("cp.async.wait_group %0;" :: "n"(n) : "memory")

// ============================ kW: wfc1 -> rna tf32 ============================
__global__ __launch_bounds__(256) void kW(const float* __restrict__ wfc1) {
    int i = blockIdx.x * 256 + threadIdx.x;   // 64 blocks: 16384 float4
    float4 v = ((const float4*)wfc1)[i];
    uint4 t;
    t.x = f2tf32(v.x); t.y = f2tf32(v.y); t.z = f2tf32(v.z); t.w = f2tf32(v.w);
    ((uint4*)g_W1t)[i] = t;
}

// ============================ fused precompute kA ============================
// Phase 1: P[f,c] = relu(E[f,:] @ w1[c,:] + b1[c])   (P kept in smem)
// Phase 2: Q[f,d] = P[f,:] @ w2[d,:,m]
__device__ __forceinline__ void block_map(int b, int& table, int& gbase, int& lbase, int& rows) {
    if (b < 11)       { table = 0; int f = b * 32;         lbase = f; gbase = f;           rows = min(32, F0 - f); }
    else if (b < 194) { table = 1; int f = (b - 11) * 32;  lbase = f; gbase = F0 + f;      rows = min(32, F1 - f); }
    else              { table = 2; int f = (b - 194) * 32; lbase = f; gbase = F0 + F1 + f; rows = min(32, F2 - f); }
}

#define KA_OFF_ES  33024            // after union(w1s 256*129=33024, w2s 32*257=8224)
#define KA_OFF_PS  (33024 + 4096)
#define SMEM_KA    ((33024 + 4096 + 8192) * 4)

__global__ __launch_bounds__(256) void kA(
    const float* __restrict__ emb0, const float* __restrict__ emb1,
    const float* __restrict__ emb2,
    const float* __restrict__ w1, const float* __restrict__ b1,
    const float* __restrict__ w2)
{
    extern __shared__ float sm[];
    float* w1s = sm;                // [256][129]
    float* w2s = sm;                // phase-2 overlay [32][257]
    float* Es  = sm + KA_OFF_ES;    // [32][128]
    float* Ps  = sm + KA_OFF_PS;    // [32][256]

    int table, gbase, lbase, rows;
    block_map(blockIdx.x, table, gbase, lbase, rows);
    const float* E = (table == 0) ? emb0 : ((table == 1) ? emb1 : emb2);
    int m = table;
    int tid = threadIdx.x;

    for (int idx = tid; idx < 256 * 128; idx += 256) {
        int c = idx >> 7, r = idx & 127;
        w1s[c * 129 + r] = w1[idx];
    }
    for (int idx = tid; idx < 32 * 128; idx += 256) {
        int rr = idx >> 7, r = idx & 127;
        Es[idx] = (rr < rows) ? E[(long long)(lbase + rr) * RK + r] : 0.f;
    }
    __syncthreads();

    int tc = tid & 31, tr = tid >> 5;
    {
        float acc[8][4];
        #pragma unroll
        for (int i = 0; i < 8; i++)
            #pragma unroll
            for (int q = 0; q < 4; q++) acc[i][q] = 0.f;
        #pragma unroll 4
        for (int r = 0; r < 128; r++) {
            float w[8], e[4];
            #pragma unroll
            for (int cc = 0; cc < 8; cc++) w[cc] = w1s[(tc + 32 * cc) * 129 + r];
            #pragma unroll
            for (int q = 0; q < 4; q++) e[q] = Es[(tr * 4 + q) * 128 + r];
            #pragma unroll
            for (int cc = 0; cc < 8; cc++)
                #pragma unroll
                for (int q = 0; q < 4; q++) acc[cc][q] += w[cc] * e[q];
        }
        #pragma unroll
        for (int cc = 0; cc < 8; cc++) {
            int c = tc + 32 * cc;
            float bb = b1[c];
            #pragma unroll
            for (int q = 0; q < 4; q++) {
                float v = acc[cc][q] + bb;
                Ps[(tr * 4 + q) * 256 + c] = v > 0.f ? v : 0.f;
            }
        }
    }
    __syncthreads();   // Ps ready; w1s dead -> w2s overlay

    float acc[8][4];
    #pragma unroll
    for (int i = 0; i < 8; i++)
        #pragma unroll
        for (int q = 0; q < 4; q++) acc[i][q] = 0.f;

    for (int c0 = 0; c0 < 256; c0 += 32) {
        __syncthreads();
        for (int i = 0; i < 32; i++) {
            int lin = tid + i * 256;
            int d = lin >> 5, cl = lin & 31;
            w2s[cl * 257 + d] = w2[d * 768 + (c0 + cl) * 3 + m];
        }
        __syncthreads();
        #pragma unroll 4
        for (int c = 0; c < 32; c++) {
            float w[8], p[4];
            #pragma unroll
            for (int dd = 0; dd < 8; dd++) w[dd] = w2s[c * 257 + tc + 32 * dd];
            #pragma unroll
            for (int q = 0; q < 4; q++) p[q] = Ps[(tr * 4 + q) * 256 + c0 + c];
            #pragma unroll
            for (int dd = 0; dd < 8; dd++)
                #pragma unroll
                for (int q = 0; q < 4; q++) acc[dd][q] += w[dd] * p[q];
        }
    }
    #pragma unroll
    for (int dd = 0; dd < 8; dd++) {
        int d = tc + 32 * dd;
        #pragma unroll
        for (int q = 0; q < 4; q++) {
            int rr = tr * 4 + q;
            if (rr < rows) g_Q[(gbase + rr) * CH + d] = acc[dd][q];
        }
    }
}

// ============================ kernel B ============================
// 512 threads, 16 warps = 4(M) x 4(N), 128 samples/CTA.
// Gather h0 (cols 0..127) up front; gather h1 pipelined into MMA chunks 0..3.
#define SA 260
#define SB 36
#define NCH 8
#define BUF_F 9216                    // 256*36
#define OFF_B    33800                // As = 128*260 (rounded)
#define OFF_IDX  52232
#define OFF_BF1  52616
#define OFF_WF2  52872
#define OFF_PS   53128                // 512 floats
#define OFF_FLAG 53640
#define SMEM_KB ((53644) * 4)

__global__ __launch_bounds__(512) void kB_mma(
    const void* __restrict__ indices,
    const float* __restrict__ b2,
    const float* __restrict__ bfc1,
    const float* __restrict__ wfc2, const float* __restrict__ bfc2,
    float* __restrict__ out, int B)
{
    extern __shared__ float sm[];
    float* As   = sm;
    float* Bs   = sm + OFF_B;
    int*   idxs = (int*)(sm + OFF_IDX);
    float* bf1s = sm + OFF_BF1;
    float* wf2s = sm + OFF_WF2;
    float* psum = sm + OFF_PS;
    int*   flagp = (int*)(sm + OFF_FLAG);
    const uint32_t sb = smem_u32(sm);

    int tid = threadIdx.x;
    int w = tid >> 5, lane = tid & 31;
    int g = lane >> 2, tig = lane & 3;
    int wm = w & 3, wn = w >> 2;
    int b0 = blockIdx.x * 128;

    // ---- prefetch B chunk 0 (g_W1t, already rna-tf32) ----
    {
        const float* src0 = g_W1t;
        #pragma unroll
        for (int i = 0; i < 4; ++i) {
            int lin = tid + i * 512;
            int n = lin >> 3, f4 = lin & 7;
            uint32_t dst = sb + (uint32_t)(OFF_B + n * SB + f4 * 4) * 4u;
            CP_ASYNC16(dst, src0 + n * 256 + f4 * 4);
        }
        CP_COMMIT();
    }

    // ---- per-CTA index dtype detection (warp 0, first 256 words, dtype-safe) ----
    if (w == 0) {
        const uint32_t* rw = (const uint32_t*)indices;
        uint32_t v = rw[lane * 8 + 1] | rw[lane * 8 + 3] | rw[lane * 8 + 5] | rw[lane * 8 + 7];
        int all0 = __all_sync(0xffffffffu, v == 0u);
        if (lane == 0) *flagp = all0;
    }
    if (tid >= 32 && tid < 288) bf1s[tid - 32] = bfc1[tid - 32];
    else if (tid >= 288 && tid < 512) wf2s[tid - 288] = wfc2[tid - 288];
    __syncthreads();
    if (tid >= 32 && tid < 64) wf2s[224 + (tid - 32)] = wfc2[224 + (tid - 32)];

    // ---- indices ----
    int is64 = *flagp;
    if (tid < 128) {
        long long sg = b0 + tid;
        if (sg > (long long)B - 1) sg = B - 1;
        long long bb = sg * 3;
        int i0, i1, i2;
        if (is64) {
            const long long* ip = (const long long*)indices;
            i0 = (int)ip[bb]; i1 = (int)ip[bb + 1]; i2 = (int)ip[bb + 2];
        } else {
            const int* ip = (const int*)indices;
            i0 = ip[bb]; i1 = ip[bb + 1]; i2 = ip[bb + 2];
        }
        idxs[tid * 3] = i0; idxs[tid * 3 + 1] = i1; idxs[tid * 3 + 2] = i2;
    }
    __syncthreads();

    const float4* Q0 = (const float4*)g_Q;
    const float4* Q1 = (const float4*)(g_Q + F0 * CH);
    const float4* Q2 = (const float4*)(g_Q + (F0 + F1) * CH);
    const float4* b2v = (const float4*)b2;
    float4 d0 = b2v[lane];
    float4 d1 = b2v[lane + 32];

    // ---- gather h0: cols 0..127 for all 8 samples of this warp ----
    #pragma unroll 4
    for (int it = 0; it < 8; ++it) {
        int s = w * 8 + it;
        int i0 = idxs[s * 3], i1 = idxs[s * 3 + 1], i2 = idxs[s * 3 + 2];
        int f4 = lane;
        float4 a = Q0[i0 * 64 + f4];
        float4 bq = Q1[i1 * 64 + f4];
        float4 cq = Q2[i2 * 64 + f4];
        uint4 t;
        t.x = f2tf32(fmaxf(a.x + bq.x + cq.x + d0.x, 0.f));
        t.y = f2tf32(fmaxf(a.y + bq.y + cq.y + d0.y, 0.f));
        t.z = f2tf32(fmaxf(a.z + bq.z + cq.z + d0.z, 0.f));
        t.w = f2tf32(fmaxf(a.w + bq.w + cq.w + d0.w, 0.f));
        *(uint4*)(As + s * SA + f4 * 4) = t;
    }

    // ---- GEMM over 8 K-chunks; h1 gather pipelined into chunks 0..3 ----
    float acc[2][8][4];
    #pragma unroll
    for (int mt = 0; mt < 2; mt++)
        #pragma unroll
        for (int nt = 0; nt < 8; nt++)
            #pragma unroll
            for (int q = 0; q < 4; q++) acc[mt][nt][q] = 0.f;

    for (int c = 0; c < NCH; ++c) {
        if (c + 1 < NCH) {
            int buf = (c + 1) & 1;
            const float* src = g_W1t + (c + 1) * 32;
            #pragma unroll
            for (int i = 0; i < 4; ++i) {
                int lin = tid + i * 512;
                int n = lin >> 3, f4 = lin & 7;
                uint32_t dst = sb + (uint32_t)(OFF_B + buf * BUF_F + n * SB + f4 * 4) * 4u;
                CP_ASYNC16(dst, src + n * 256 + f4 * 4);
            }
            CP_COMMIT();
            CP_WAIT(1);
        } else {
            CP_WAIT(0);
        }
        __syncthreads();

        // issue h1 gather LDGs (2 samples per warp per chunk) BEFORE the MMA block
        float4 ga[2][3];
        int srow[2];
        if (c < 4) {
            #pragma unroll
            for (int t = 0; t < 2; ++t) {
                int s = w * 8 + 2 * c + t;
                srow[t] = s;
                int i0 = idxs[s * 3], i1 = idxs[s * 3 + 1], i2 = idxs[s * 3 + 2];
                int f4 = lane + 32;
                ga[t][0] = Q0[i0 * 64 + f4];
                ga[t][1] = Q1[i1 * 64 + f4];
                ga[t][2] = Q2[i2 * 64 + f4];
            }
        }

        const float* Bb = Bs + (c & 1) * BUF_F;
        #pragma unroll
        for (int kk = 0; kk < 4; ++kk) {
            int kg = c * 32 + kk * 8;
            int kl = kk * 8;
            uint32_t a[2][4], b[8][2];
            #pragma unroll
            for (int mt = 0; mt < 2; ++mt) {
                const float* ap = As + (wm * 32 + mt * 16 + g) * SA + kg + tig;
                a[mt][0] = __float_as_uint(ap[0]);
                a[mt][1] = __float_as_uint(ap[8 * SA]);
                a[mt][2] = __float_as_uint(ap[4]);
                a[mt][3] = __float_as_uint(ap[8 * SA + 4]);
            }
            #pragma unroll
            for (int nt = 0; nt < 8; ++nt) {
                const float* bp = Bb + (wn * 64 + nt * 8 + g) * SB + kl + tig;
                b[nt][0] = __float_as_uint(bp[0]);
                b[nt][1] = __float_as_uint(bp[4]);
            }
            #pragma unroll
            for (int mt = 0; mt < 2; ++mt)
                #pragma unroll
                for (int nt = 0; nt < 8; ++nt)
                    MMA_TF32(acc[mt][nt], a[mt], b[nt]);
        }

        // combine + store h1 rows (cols 128..255; chunks 0..3 only read cols <128)
        if (c < 4) {
            #pragma unroll
            for (int t = 0; t < 2; ++t) {
                uint4 o;
                o.x = f2tf32(fmaxf(ga[t][0].x + ga[t][1].x + ga[t][2].x + d1.x, 0.f));
                o.y = f2tf32(fmaxf(ga[t][0].y + ga[t][1].y + ga[t][2].y + d1.y, 0.f));
                o.z = f2tf32(fmaxf(ga[t][0].z + ga[t][1].z + ga[t][2].z + d1.z, 0.f));
                o.w = f2tf32(fmaxf(ga[t][0].w + ga[t][1].w + ga[t][2].w + d1.w, 0.f));
                *(uint4*)(As + srow[t] * SA + (lane + 32) * 4) = o;
            }
        }
        __syncthreads();
    }

    // ---- epilogue: fc1 bias+relu, fc2 dot, quad reduce, combine 4 N-quadrants ----
    #pragma unroll
    for (int mt = 0; mt < 2; ++mt) {
        float p0 = 0.f, p1 = 0.f;
        #pragma unroll
        for (int nt = 0; nt < 8; ++nt) {
            int j = wn * 64 + nt * 8 + tig * 2;
            float bj0 = bf1s[j], bj1 = bf1s[j + 1];
            float wj0 = wf2s[j], wj1 = wf2s[j + 1];
            float h;
            h = acc[mt][nt][0] + bj0; h = h > 0.f ? h : 0.f; p0 += h * wj0;
            h = acc[mt][nt][1] + bj1; h = h > 0.f ? h : 0.f; p0 += h * wj1;
            h = acc[mt][nt][2] + bj0; h = h > 0.f ? h : 0.f; p1 += h * wj0;
            h = acc[mt][nt][3] + bj1; h = h > 0.f ? h : 0.f; p1 += h * wj1;
        }
        p0 += __shfl_xor_sync(0xffffffffu, p0, 1);
        p0 += __shfl_xor_sync(0xffffffffu, p0, 2);
        p1 += __shfl_xor_sync(0xffffffffu, p1, 1);
        p1 += __shfl_xor_sync(0xffffffffu, p1, 2);
        if (tig == 0) {
            int r = wm * 32 + mt * 16 + g;
            psum[wn * 128 + r] = p0;
            psum[wn * 128 + r + 8] = p1;
        }
    }
    __syncthreads();
    if (tid < 128) {
        int sg = b0 + tid;
        if (sg < B)
            out[sg] = fmaxf(psum[tid] + psum[128 + tid] + psum[256 + tid] + psum[384 + tid] + bfc2[0], 0.f);
    }
}

// ============================ launch ============================
extern "C" void kernel_launch(void* const* d_in, const int* in_sizes, int n_in,
                              void* d_out, int out_size)
{
    const void*  indices = d_in[0];
    const float* emb0 = (const float*)d_in[1];
    const float* emb1 = (const float*)d_in[2];
    const float* emb2 = (const float*)d_in[3];
    const float* w1   = (const float*)d_in[4];
    const float* b1   = (const float*)d_in[5];
    const float* w2   = (const float*)d_in[6];
    const float* b2   = (const float*)d_in[7];
    const float* wfc1 = (const float*)d_in[8];
    const float* bfc1 = (const float*)d_in[9];
    const float* wfc2 = (const float*)d_in[10];
    const float* bfc2 = (const float*)d_in[11];
    float* out = (float*)d_out;

    int B = in_sizes[0] / 3;

    cudaFuncSetAttribute(kA,     cudaFuncAttributeMaxDynamicSharedMemorySize, SMEM_KA);
    cudaFuncSetAttribute(kB_mma, cudaFuncAttributeMaxDynamicSharedMemorySize, SMEM_KB);

    kW<<<64, 256>>>(wfc1);
    kA<<<196, 256, SMEM_KA>>>(emb0, emb1, emb2, w1, b1, w2);
    int nb = (B + 127) / 128;
    kB_mma<<<nb, 512, SMEM_KB>>>(indices, b2, bfc1, wfc2, bfc2, out, B);
}

// round 8
// speedup vs baseline: 1.0691x; 1.0691x over previous
#include <cuda_runtime.h>
#include <cuda_bf16.h>
#include <cstdint>

#define F0 339
#define F1 5825
#define F2 64
#define NROWS 6228
#define RK 128
#define CH 256

__device__ __align__(16) float g_Q[NROWS * CH];
// pre-split weights (bf16 hi/lo planes)
__device__ __align__(16) __nv_bfloat16 g_W1hi[256 * 128], g_W1lo[256 * 128];     // conv1 [c][r]
__device__ __align__(16) __nv_bfloat16 g_W2hi[3 * 256 * 256], g_W2lo[3 * 256 * 256]; // [m][d][c]
__device__ __align__(16) __nv_bfloat16 g_Wfhi[256 * 256], g_Wflo[256 * 256];     // fc1 [j][k]

// ============================ primitives ============================
__device__ __forceinline__ uint32_t smem_u32(const void* p) {
    uint32_t a;
    asm("{ .reg .u64 t; cvta.to.shared.u64 t, %1; cvt.u32.u64 %0, t; }" : "=r"(a) : "l"(p));
    return a;
}
#define LDSM_X4(r0, r1, r2, r3, addr) \
    asm volatile("ldmatrix.sync.aligned.m8n8.x4.shared.b16 {%0,%1,%2,%3}, [%4];" \
        : "=r"(r0), "=r"(r1), "=r"(r2), "=r"(r3) : "r"(addr))
#define MMA_BF16(d, a, b0, b1) \
    asm volatile("mma.sync.aligned.m16n8k16.row.col.f32.bf16.bf16.f32 " \
        "{%0,%1,%2,%3}, {%4,%5,%6,%7}, {%8,%9}, {%0,%1,%2,%3};" \
        : "+f"((d)[0]), "+f"((d)[1]), "+f"((d)[2]), "+f"((d)[3]) \
        : "r"((a)[0]), "r"((a)[1]), "r"((a)[2]), "r"((a)[3]), "r"(b0), "r"(b1))
#define CP_ASYNC16(dst, src) \
    asm volatile("cp.async.cg.shared.global [%0], [%1], 16;" :: "r"(dst), "l"(src))
#define CP_COMMIT() asm volatile("cp.async.commit_group;" ::: "memory")
#define CP_WAIT0()  asm volatile("cp.async.wait_group 0;" ::: "memory")
#define CP_WAIT1()  asm volatile("cp.async.wait_group 1;" ::: "memory")

__device__ __forceinline__ void bfsplit(float x, __nv_bfloat16& h, __nv_bfloat16& l) {
    h = __float2bfloat16_rn(x);
    l = __float2bfloat16_rn(x - __bfloat162float(h));
}
__device__ __forceinline__ uint32_t pk(__nv_bfloat16 a, __nv_bfloat16 b) {
    __nv_bfloat162 t; t.x = a; t.y = b;
    return *reinterpret_cast<uint32_t*>(&t);
}
__device__ __forceinline__ float frelu(float x) { return x > 0.f ? x : 0.f; }

// ============================ B-chunk staging ============================
// chunk = 32 k. smem chunk layout per plane: 256 rows x (32+8 pad) bf16 = 80B rows.
// plane size 20480B; hi at +0, lo at +20480. One buffer = 40960B.
__device__ __forceinline__ void stageB(uint32_t dbuf,
    const __nv_bfloat16* __restrict__ gBhi, const __nv_bfloat16* __restrict__ gBlo,
    int Ksrc, int c, int tid)
{
    #pragma unroll
    for (int it = 0; it < 4; ++it) {
        int idx = tid + it * 512;
        int pl = idx >> 10, rem = idx & 1023;
        int n = rem >> 2, g = rem & 3;
        const __nv_bfloat16* src = (pl ? gBlo : gBhi) + n * Ksrc + c * 32 + g * 8;
        CP_ASYNC16(dbuf + (uint32_t)(pl * 20480 + n * 80 + g * 16), src);
    }
    CP_COMMIT();
}

// ============================ bf16x3 mainloop ============================
// M=128, N=256, K=NCHUNK*32. 512 threads, 16 warps = 4(M)x4(N), warp tile 32x64.
// A resident in smem planes (hi at sbA, lo at +128*NG*16), row stride NG granules,
// XOR swizzle g^= (row&7). B staged per chunk from global bf16 [n][k] planes.
template<int NCHUNK, int NG, bool DB>
__device__ __forceinline__ void gemm_bf16x3(
    uint32_t sbA, uint32_t sbB,
    const __nv_bfloat16* __restrict__ gBhi, const __nv_bfloat16* __restrict__ gBlo,
    int Ksrc, float (&acc)[2][8][4], bool prestaged)
{
    const int tid = threadIdx.x;
    const int lane = tid & 31;
    const int w = tid >> 5;
    const int wm = w & 3, wn = w >> 2;
    const int q = lane >> 3, rl = lane & 7;
    constexpr uint32_t APLANE = 128u * NG * 16u;

    if (!prestaged) stageB(sbB, gBhi, gBlo, Ksrc, 0, tid);

    const int rA0 = wm * 32 + rl + (q & 1) * 8;        // + mt*16
    const int nB0 = wn * 64 + rl + (q >> 1) * 8;       // + ntp*16
    const int gA  = (q >> 1);                          // + c*4 + ks*2
    const int gB  = (q & 1);                           // + ks*2

    for (int c = 0; c < NCHUNK; ++c) {
        if (DB) {
            if (c + 1 < NCHUNK) {
                stageB(sbB + (uint32_t)(((c + 1) & 1) * 40960), gBhi, gBlo, Ksrc, c + 1, tid);
                CP_WAIT1();
            } else CP_WAIT0();
        } else {
            CP_WAIT0();
        }
        __syncthreads();
        uint32_t cur = DB ? sbB + (uint32_t)((c & 1) * 40960) : sbB;

        #pragma unroll
        for (int ks = 0; ks < 2; ++ks) {
            uint32_t ah[2][4], al[2][4];
            #pragma unroll
            for (int mt = 0; mt < 2; ++mt) {
                int r = rA0 + mt * 16;
                int g = c * 4 + ks * 2 + gA;
                uint32_t ad = sbA + (uint32_t)((r * NG + (g ^ (r & 7))) << 4);
                LDSM_X4(ah[mt][0], ah[mt][1], ah[mt][2], ah[mt][3], ad);
                LDSM_X4(al[mt][0], al[mt][1], al[mt][2], al[mt][3], ad + APLANE);
            }
            #pragma unroll
            for (int ntp = 0; ntp < 4; ++ntp) {
                int n = nB0 + ntp * 16;
                uint32_t bd = cur + (uint32_t)(n * 80 + (ks * 2 + gB) * 16);
                uint32_t bh[4], bl[4];
                LDSM_X4(bh[0], bh[1], bh[2], bh[3], bd);
                LDSM_X4(bl[0], bl[1], bl[2], bl[3], bd + 20480);
                #pragma unroll
                for (int mt = 0; mt < 2; ++mt) {
                    MMA_BF16(acc[mt][ntp * 2],     ah[mt], bh[0], bh[1]);
                    MMA_BF16(acc[mt][ntp * 2],     al[mt], bh[0], bh[1]);
                    MMA_BF16(acc[mt][ntp * 2],     ah[mt], bl[0], bl[1]);
                    MMA_BF16(acc[mt][ntp * 2 + 1], ah[mt], bh[2], bh[3]);
                    MMA_BF16(acc[mt][ntp * 2 + 1], al[mt], bh[2], bh[3]);
                    MMA_BF16(acc[mt][ntp * 2 + 1], ah[mt], bl[2], bl[3]);
                }
            }
        }
        __syncthreads();
        if (!DB && c + 1 < NCHUNK) stageB(sbB, gBhi, gBlo, Ksrc, c + 1, tid);
    }
}

// ============================ kW: split all weights to bf16 hi/lo ============================
__global__ __launch_bounds__(256) void kW(
    const float* __restrict__ w1, const float* __restrict__ wfc1, const float* __restrict__ w2)
{
    int e = blockIdx.x * 256 + threadIdx.x;
    __nv_bfloat16 h, l;
    if (e < 32768) {                       // w1 [c][r] -> same layout
        bfsplit(w1[e], h, l);
        g_W1hi[e] = h; g_W1lo[e] = l;
    } else if (e < 98304) {                // wfc1 [j][k]
        int i = e - 32768;
        bfsplit(wfc1[i], h, l);
        g_Wfhi[i] = h; g_Wflo[i] = l;
    } else {                               // w2 [d][c][m] -> [m][d][c]
        int i = e - 98304;                 // i = m*65536 + d*256 + c
        int m = i >> 16, r = i & 65535, d = r >> 8, cc = r & 255;
        bfsplit(w2[d * 768 + cc * 3 + m], h, l);
        g_W2hi[i] = h; g_W2lo[i] = l;
    }
}

// ============================ kA: precompute Q (tensorized) ============================
// Block = 128 rows of the concatenated table. Phase1: P = relu(E@W1^T + b1) (M=128,N=256,K=128)
// Phase2: Q = P @ W2m^T (M=128,N=256,K=256).
// smem: [0,131072) P planes (first 40960 doubles as phase1 B staging);
//       [131072,196608) E planes (phase2 B staging overlays this region);
//       [196608,197632) b1s.
#define KA_P    0u
#define KA_AE   131072u
#define KA_STG2 131072u
#define KA_B1   196608
#define SMEM_KA 197632

__global__ __launch_bounds__(512) void kA(
    const float* __restrict__ emb0, const float* __restrict__ emb1,
    const float* __restrict__ emb2, const float* __restrict__ b1)
{
    extern __shared__ char smc[];
    const uint32_t sb = smem_u32(smc);
    float* b1s = (float*)(smc + KA_B1);
    const int tid = threadIdx.x;
    const int lane = tid & 31, w = tid >> 5;
    const int wm = w & 3, wn = w >> 2;
    const int g4 = lane >> 2, tig = lane & 3;

    // block -> table mapping (128-row blocks: 3 + 46 + 1 = 50)
    int b = blockIdx.x, table, gbase, lbase, rows;
    if (b < 3)       { table = 0; int f = b * 128;        lbase = f; gbase = f;           rows = min(128, F0 - f); }
    else if (b < 49) { table = 1; int f = (b - 3) * 128;  lbase = f; gbase = F0 + f;      rows = min(128, F1 - f); }
    else             { table = 2; lbase = 0;              gbase = F0 + F1;                rows = F2; }
    const float* E = (table == 0) ? emb0 : ((table == 1) ? emb1 : emb2);

    if (tid < 256) b1s[tid] = b1[tid];

    // fill E planes: 128 rows x 16 granules (K=128), clamped rows
    {
        #pragma unroll
        for (int it = 0; it < 4; ++it) {
            int idx = tid + it * 512;
            int row = idx >> 4, g = idx & 15;
            int er = lbase + min(row, rows - 1);
            const float4* src = (const float4*)(E + (long long)er * RK + g * 8);
            float4 v0 = src[0], v1 = src[1];
            __nv_bfloat16 h[8], l[8];
            bfsplit(v0.x, h[0], l[0]); bfsplit(v0.y, h[1], l[1]);
            bfsplit(v0.z, h[2], l[2]); bfsplit(v0.w, h[3], l[3]);
            bfsplit(v1.x, h[4], l[4]); bfsplit(v1.y, h[5], l[5]);
            bfsplit(v1.z, h[6], l[6]); bfsplit(v1.w, h[7], l[7]);
            uint32_t off = KA_AE + (uint32_t)((row * 16 + (g ^ (row & 7))) << 4);
            *(uint4*)(smc + off) = make_uint4(pk(h[0], h[1]), pk(h[2], h[3]), pk(h[4], h[5]), pk(h[6], h[7]));
            *(uint4*)(smc + off + 32768) = make_uint4(pk(l[0], l[1]), pk(l[2], l[3]), pk(l[4], l[5]), pk(l[6], l[7]));
        }
    }
    __syncthreads();

    // phase 1
    float acc[2][8][4];
    #pragma unroll
    for (int mt = 0; mt < 2; mt++)
        #pragma unroll
        for (int nt = 0; nt < 8; nt++)
            #pragma unroll
            for (int p = 0; p < 4; p++) acc[mt][nt][p] = 0.f;
    gemm_bf16x3<4, 16, false>(sb + KA_AE, sb + KA_P, g_W1hi, g_W1lo, 128, acc, false);

    // phase1 epilogue: relu(acc + b1) -> P planes (NG=32), splitting to hi/lo
    #pragma unroll
    for (int mt = 0; mt < 2; ++mt) {
        #pragma unroll
        for (int nt = 0; nt < 8; ++nt) {
            int j0 = wn * 64 + nt * 8 + tig * 2;
            float v00 = frelu(acc[mt][nt][0] + b1s[j0]);
            float v01 = frelu(acc[mt][nt][1] + b1s[j0 + 1]);
            float v10 = frelu(acc[mt][nt][2] + b1s[j0]);
            float v11 = frelu(acc[mt][nt][3] + b1s[j0 + 1]);
            __nv_bfloat16 h0, l0, h1, l1;
            int rlo = wm * 32 + mt * 16 + g4;
            int rhi = rlo + 8;
            uint32_t offL = KA_P + (uint32_t)(((rlo * 32 + ((j0 >> 3) ^ (rlo & 7))) << 4) + (j0 & 7) * 2);
            uint32_t offH = KA_P + (uint32_t)(((rhi * 32 + ((j0 >> 3) ^ (rhi & 7))) << 4) + (j0 & 7) * 2);
            bfsplit(v00, h0, l0); bfsplit(v01, h1, l1);
            *(uint32_t*)(smc + offL) = pk(h0, h1);
            *(uint32_t*)(smc + offL + 65536) = pk(l0, l1);
            bfsplit(v10, h0, l0); bfsplit(v11, h1, l1);
            *(uint32_t*)(smc + offH) = pk(h0, h1);
            *(uint32_t*)(smc + offH + 65536) = pk(l0, l1);
        }
    }
    __syncthreads();

    // phase 2
    #pragma unroll
    for (int mt = 0; mt < 2; mt++)
        #pragma unroll
        for (int nt = 0; nt < 8; nt++)
            #pragma unroll
            for (int p = 0; p < 4; p++) acc[mt][nt][p] = 0.f;
    gemm_bf16x3<8, 32, false>(sb + KA_P, sb + KA_STG2,
                              g_W2hi + table * 65536, g_W2lo + table * 65536, 256, acc, false);

    // store Q (fp32)
    #pragma unroll
    for (int mt = 0; mt < 2; ++mt) {
        int rlo = wm * 32 + mt * 16 + g4;
        int rhi = rlo + 8;
        #pragma unroll
        for (int nt = 0; nt < 8; ++nt) {
            int j0 = wn * 64 + nt * 8 + tig * 2;
            if (rlo < rows) {
                float2 v = make_float2(acc[mt][nt][0], acc[mt][nt][1]);
                *(float2*)(g_Q + (gbase + rlo) * CH + j0) = v;
            }
            if (rhi < rows) {
                float2 v = make_float2(acc[mt][nt][2], acc[mt][nt][3]);
                *(float2*)(g_Q + (gbase + rhi) * CH + j0) = v;
            }
        }
    }
}

// ============================ kB: per-sample path ============================
// smem: [0,131072) A (h2) planes; [131072,212992) B double-buffer staging;
//       then idxs, bf1s, wf2s, psum, flag.
#define KB_A    0u
#define KB_STG  131072u
#define KB_IDX  212992
#define KB_BF1  214528
#define KB_WF2  215552
#define KB_PS   216576
#define KB_FLAG 218624
#define SMEM_KB 218640

__global__ __launch_bounds__(512) void kB(
    const void* __restrict__ indices,
    const float* __restrict__ b2,
    const float* __restrict__ bfc1,
    const float* __restrict__ wfc2, const float* __restrict__ bfc2,
    float* __restrict__ out, int B)
{
    extern __shared__ char smc[];
    const uint32_t sb = smem_u32(smc);
    int*   idxs = (int*)(smc + KB_IDX);
    float* bf1s = (float*)(smc + KB_BF1);
    float* wf2s = (float*)(smc + KB_WF2);
    float* psum = (float*)(smc + KB_PS);
    int*   flagp = (int*)(smc + KB_FLAG);

    const int tid = threadIdx.x;
    const int lane = tid & 31, w = tid >> 5;
    const int wm = w & 3, wn = w >> 2;
    const int g4 = lane >> 2, tig = lane & 3;
    const int b0 = blockIdx.x * 128;

    // prestage B chunk 0 (overlaps with gather below)
    stageB(sb + KB_STG, g_Wfhi, g_Wflo, 256, 0, tid);

    // index dtype detect (warp 0; dtype-safe read of first 256 words)
    if (w == 0) {
        const uint32_t* rw = (const uint32_t*)indices;
        uint32_t v = rw[lane * 8 + 1] | rw[lane * 8 + 3] | rw[lane * 8 + 5] | rw[lane * 8 + 7];
        int all0 = __all_sync(0xffffffffu, v == 0u);
        if (lane == 0) *flagp = all0;
    }
    if (tid < 256) bf1s[tid] = bfc1[tid];
    else wf2s[tid - 256] = wfc2[tid - 256];
    __syncthreads();

    const int is64 = *flagp;
    if (tid < 128) {
        long long sg = b0 + tid;
        if (sg > (long long)B - 1) sg = B - 1;
        long long bb = sg * 3;
        int i0, i1, i2;
        if (is64) {
            const long long* ip = (const long long*)indices;
            i0 = (int)ip[bb]; i1 = (int)ip[bb + 1]; i2 = (int)ip[bb + 2];
        } else {
            const int* ip = (const int*)indices;
            i0 = ip[bb]; i1 = ip[bb + 1]; i2 = ip[bb + 2];
        }
        idxs[tid * 3] = i0; idxs[tid * 3 + 1] = i1; idxs[tid * 3 + 2] = i2;
    }
    __syncthreads();

    // gather h2 = relu(Q0[i0]+Q1[i1]+Q2[i2]+b2) -> A planes (bf16 split, XOR layout)
    {
        const float4* Q0 = (const float4*)g_Q;
        const float4* Q1 = (const float4*)(g_Q + F0 * CH);
        const float4* Q2 = (const float4*)(g_Q + (F0 + F1) * CH);
        const float4* b2v = (const float4*)b2;
        float4 d0 = b2v[2 * lane], d1 = b2v[2 * lane + 1];
        #pragma unroll 2
        for (int it = 0; it < 8; ++it) {
            int s = w * 8 + it;
            int i0 = idxs[s * 3], i1 = idxs[s * 3 + 1], i2 = idxs[s * 3 + 2];
            float4 a0 = Q0[i0 * 64 + 2 * lane], a1 = Q0[i0 * 64 + 2 * lane + 1];
            float4 c0 = Q1[i1 * 64 + 2 * lane], c1 = Q1[i1 * 64 + 2 * lane + 1];
            float4 e0 = Q2[i2 * 64 + 2 * lane], e1 = Q2[i2 * 64 + 2 * lane + 1];
            float f[8];
            f[0] = frelu(a0.x + c0.x + e0.x + d0.x);
            f[1] = frelu(a0.y + c0.y + e0.y + d0.y);
            f[2] = frelu(a0.z + c0.z + e0.z + d0.z);
            f[3] = frelu(a0.w + c0.w + e0.w + d0.w);
            f[4] = frelu(a1.x + c1.x + e1.x + d1.x);
            f[5] = frelu(a1.y + c1.y + e1.y + d1.y);
            f[6] = frelu(a1.z + c1.z + e1.z + d1.z);
            f[7] = frelu(a1.w + c1.w + e1.w + d1.w);
            __nv_bfloat16 h[8], l[8];
            #pragma unroll
            for (int i = 0; i < 8; ++i) bfsplit(f[i], h[i], l[i]);
            uint32_t off = KB_A + (uint32_t)((s * 32 + (lane ^ (s & 7))) << 4);
            *(uint4*)(smc + off) = make_uint4(pk(h[0], h[1]), pk(h[2], h[3]), pk(h[4], h[5]), pk(h[6], h[7]));
            *(uint4*)(smc + off + 65536) = make_uint4(pk(l[0], l[1]), pk(l[2], l[3]), pk(l[4], l[5]), pk(l[6], l[7]));
        }
    }

    // GEMM: h3 = h2 @ wfc1^T  (chunk 0 prestaged)
    float acc[2][8][4];
    #pragma unroll
    for (int mt = 0; mt < 2; mt++)
        #pragma unroll
        for (int nt = 0; nt < 8; nt++)
            #pragma unroll
            for (int p = 0; p < 4; p++) acc[mt][nt][p] = 0.f;
    gemm_bf16x3<8, 32, true>(sb + KB_A, sb + KB_STG, g_Wfhi, g_Wflo, 256, acc, true);

    // epilogue: fc1 bias+relu, fc2 dot, quad reduce, combine 4 N-quadrants
    #pragma unroll
    for (int mt = 0; mt < 2; ++mt) {
        float p0 = 0.f, p1 = 0.f;
        #pragma unroll
        for (int nt = 0; nt < 8; ++nt) {
            int j = wn * 64 + nt * 8 + tig * 2;
            float bj0 = bf1s[j], bj1 = bf1s[j + 1];
            float wj0 = wf2s[j], wj1 = wf2s[j + 1];
            p0 += frelu(acc[mt][nt][0] + bj0) * wj0;
            p0 += frelu(acc[mt][nt][1] + bj1) * wj1;
            p1 += frelu(acc[mt][nt][2] + bj0) * wj0;
            p1 += frelu(acc[mt][nt][3] + bj1) * wj1;
        }
        p0 += __shfl_xor_sync(0xffffffffu, p0, 1);
        p0 += __shfl_xor_sync(0xffffffffu, p0, 2);
        p1 += __shfl_xor_sync(0xffffffffu, p1, 1);
        p1 += __shfl_xor_sync(0xffffffffu, p1, 2);
        if (tig == 0) {
            int r = wm * 32 + mt * 16 + g4;
            psum[wn * 128 + r] = p0;
            psum[wn * 128 + r + 8] = p1;
        }
    }
    __syncthreads();
    if (tid < 128) {
        int sg = b0 + tid;
        if (sg < B)
            out[sg] = frelu(psum[tid] + psum[128 + tid] + psum[256 + tid] + psum[384 + tid] + bfc2[0]);
    }
}

// ============================ launch ============================
extern "C" void kernel_launch(void* const* d_in, const int* in_sizes, int n_in,
                              void* d_out, int out_size)
{
    const void*  indices = d_in[0];
    const float* emb0 = (const float*)d_in[1];
    const float* emb1 = (const float*)d_in[2];
    const float* emb2 = (const float*)d_in[3];
    const float* w1   = (const float*)d_in[4];
    const float* b1   = (const float*)d_in[5];
    const float* w2   = (const float*)d_in[6];
    const float* b2   = (const float*)d_in[7];
    const float* wfc1 = (const float*)d_in[8];
    const float* bfc1 = (const float*)d_in[9];
    const float* wfc2 = (const float*)d_in[10];
    const float* bfc2 = (const float*)d_in[11];
    float* out = (float*)d_out;

    int B = in_sizes[0] / 3;

    cudaFuncSetAttribute(kA, cudaFuncAttributeMaxDynamicSharedMemorySize, SMEM_KA);
    cudaFuncSetAttribute(kB, cudaFuncAttributeMaxDynamicSharedMemorySize, SMEM_KB);

    kW<<<1152, 256>>>(w1, wfc1, w2);
    kA<<<50, 512, SMEM_KA>>>(emb0, emb1, emb2, b1);
    int nb = (B + 127) / 128;
    kB<<<nb, 512, SMEM_KB>>>(indices, b2, bfc1, wfc2, bfc2, out, B);
}

// round 11
// speedup vs baseline: 1.4631x; 1.3685x over previous
#include <cuda_runtime.h>
#include <cuda_bf16.h>
#include <cuda_fp16.h>
#include <cstdint>

#define F0 339
#define F1 5825
#define F2 64
#define NROWS 6228
#define RK 128
#define CH 256

__device__ __align__(16) float g_Q[NROWS * CH];
// kA weights (bf16 hi/lo planes)
__device__ __align__(16) __nv_bfloat16 g_W1hi[256 * 128], g_W1lo[256 * 128];         // conv1 [c][r]
__device__ __align__(16) __nv_bfloat16 g_W2hi[3 * 256 * 256], g_W2lo[3 * 256 * 256]; // [m][d][c]
// kB weights (fp16 hi/lo planes)
__device__ __align__(16) __half g_WFhi[256 * 256], g_WFlo[256 * 256];                // fc1 [j][k]

// ============================ primitives ============================
__device__ __forceinline__ uint32_t smem_u32(const void* p) {
    uint32_t a;
    asm("{ .reg .u64 t; cvta.to.shared.u64 t, %1; cvt.u32.u64 %0, t; }" : "=r"(a) : "l"(p));
    return a;
}
#define LDSM_X4(r0, r1, r2, r3, addr) \
    asm volatile("ldmatrix.sync.aligned.m8n8.x4.shared.b16 {%0,%1,%2,%3}, [%4];" \
        : "=r"(r0), "=r"(r1), "=r"(r2), "=r"(r3) : "r"(addr))
#define MMA_BF16(d, a, b0, b1) \
    asm volatile("mma.sync.aligned.m16n8k16.row.col.f32.bf16.bf16.f32 " \
        "{%0,%1,%2,%3}, {%4,%5,%6,%7}, {%8,%9}, {%0,%1,%2,%3};" \
        : "+f"((d)[0]), "+f"((d)[1]), "+f"((d)[2]), "+f"((d)[3]) \
        : "r"((a)[0]), "r"((a)[1]), "r"((a)[2]), "r"((a)[3]), "r"(b0), "r"(b1))
#define MMA_F16(d, a, b0, b1) \
    asm volatile("mma.sync.aligned.m16n8k16.row.col.f32.f16.f16.f32 " \
        "{%0,%1,%2,%3}, {%4,%5,%6,%7}, {%8,%9}, {%0,%1,%2,%3};" \
        : "+f"((d)[0]), "+f"((d)[1]), "+f"((d)[2]), "+f"((d)[3]) \
        : "r"((a)[0]), "r"((a)[1]), "r"((a)[2]), "r"((a)[3]), "r"(b0), "r"(b1))
#define CP_ASYNC16(dst, src) \
    asm volatile("cp.async.cg.shared.global [%0], [%1], 16;" :: "r"(dst), "l"(src))
#define CP_COMMIT() asm volatile("cp.async.commit_group;" ::: "memory")
#define CP_WAIT0()  asm volatile("cp.async.wait_group 0;" ::: "memory")
#define CP_WAIT1()  asm volatile("cp.async.wait_group 1;" ::: "memory")

__device__ __forceinline__ void bfsplit(float x, __nv_bfloat16& h, __nv_bfloat16& l) {
    h = __float2bfloat16_rn(x);
    l = __float2bfloat16_rn(x - __bfloat162float(h));
}
__device__ __forceinline__ void hsplit(float x, __half& h, __half& l) {
    h = __float2half_rn(x);
    l = __float2half_rn(x - __half2float(h));
}
__device__ __forceinline__ uint32_t pk(__nv_bfloat16 a, __nv_bfloat16 b) {
    __nv_bfloat162 t; t.x = a; t.y = b;
    return *reinterpret_cast<uint32_t*>(&t);
}
__device__ __forceinline__ uint32_t pkh(__half a, __half b) {
    __half2 t; t.x = a; t.y = b;
    return *reinterpret_cast<uint32_t*>(&t);
}
__device__ __forceinline__ float frelu(float x) { return x > 0.f ? x : 0.f; }

// ============================ bf16 B staging (kA, 512 thr, 80B rows) ============================
__device__ __forceinline__ void stageB(uint32_t dbuf,
    const __nv_bfloat16* __restrict__ gBhi, const __nv_bfloat16* __restrict__ gBlo,
    int Ksrc, int c, int tid)
{
    #pragma unroll
    for (int it = 0; it < 4; ++it) {
        int idx = tid + it * 512;
        int pl = idx >> 10, rem = idx & 1023;
        int n = rem >> 2, g = rem & 3;
        const __nv_bfloat16* src = (pl ? gBlo : gBhi) + n * Ksrc + c * 32 + g * 8;
        CP_ASYNC16(dbuf + (uint32_t)(pl * 20480 + n * 80 + g * 16), src);
    }
    CP_COMMIT();
}

// ============================ bf16x3 mainloop (kA; 512 thr, 16 warps) ============================
template<int NCHUNK, int NG, bool DB>
__device__ __forceinline__ void gemm_bf16x3(
    uint32_t sbA, uint32_t sbB,
    const __nv_bfloat16* __restrict__ gBhi, const __nv_bfloat16* __restrict__ gBlo,
    int Ksrc, float (&acc)[2][8][4], bool prestaged)
{
    const int tid = threadIdx.x;
    const int lane = tid & 31;
    const int w = tid >> 5;
    const int wm = w & 3, wn = w >> 2;
    const int q = lane >> 3, rl = lane & 7;
    constexpr uint32_t APLANE = 128u * NG * 16u;

    if (!prestaged) stageB(sbB, gBhi, gBlo, Ksrc, 0, tid);

    const int rA0 = wm * 32 + rl + (q & 1) * 8;
    const int nB0 = wn * 64 + rl + (q >> 1) * 8;
    const int gA  = (q >> 1);
    const int gB  = (q & 1);

    for (int c = 0; c < NCHUNK; ++c) {
        if (DB) {
            if (c + 1 < NCHUNK) {
                stageB(sbB + (uint32_t)(((c + 1) & 1) * 40960), gBhi, gBlo, Ksrc, c + 1, tid);
                CP_WAIT1();
            } else CP_WAIT0();
        } else {
            CP_WAIT0();
        }
        __syncthreads();
        uint32_t cur = DB ? sbB + (uint32_t)((c & 1) * 40960) : sbB;

        #pragma unroll
        for (int ks = 0; ks < 2; ++ks) {
            uint32_t ah[2][4], al[2][4];
            #pragma unroll
            for (int mt = 0; mt < 2; ++mt) {
                int r = rA0 + mt * 16;
                int g = c * 4 + ks * 2 + gA;
                uint32_t ad = sbA + (uint32_t)((r * NG + (g ^ (r & 7))) << 4);
                LDSM_X4(ah[mt][0], ah[mt][1], ah[mt][2], ah[mt][3], ad);
                LDSM_X4(al[mt][0], al[mt][1], al[mt][2], al[mt][3], ad + APLANE);
            }
            #pragma unroll
            for (int ntp = 0; ntp < 4; ++ntp) {
                int n = nB0 + ntp * 16;
                uint32_t bd = cur + (uint32_t)(n * 80 + (ks * 2 + gB) * 16);
                uint32_t bh[4], bl[4];
                LDSM_X4(bh[0], bh[1], bh[2], bh[3], bd);
                LDSM_X4(bl[0], bl[1], bl[2], bl[3], bd + 20480);
                #pragma unroll
                for (int mt = 0; mt < 2; ++mt) {
                    MMA_BF16(acc[mt][ntp * 2],     ah[mt], bh[0], bh[1]);
                    MMA_BF16(acc[mt][ntp * 2],     al[mt], bh[0], bh[1]);
                    MMA_BF16(acc[mt][ntp * 2],     ah[mt], bl[0], bl[1]);
                    MMA_BF16(acc[mt][ntp * 2 + 1], ah[mt], bh[2], bh[3]);
                    MMA_BF16(acc[mt][ntp * 2 + 1], al[mt], bh[2], bh[3]);
                    MMA_BF16(acc[mt][ntp * 2 + 1], ah[mt], bl[2], bl[3]);
                }
            }
        }
        __syncthreads();
        if (!DB && c + 1 < NCHUNK) stageB(sbB, gBhi, gBlo, Ksrc, c + 1, tid);
    }
}

// ============================ kW: split weights ============================
__global__ __launch_bounds__(256) void kW(
    const float* __restrict__ w1, const float* __restrict__ wfc1, const float* __restrict__ w2)
{
    int e = blockIdx.x * 256 + threadIdx.x;
    if (e < 32768) {                       // w1 [c][r] bf16 split
        __nv_bfloat16 h, l;
        bfsplit(w1[e], h, l);
        g_W1hi[e] = h; g_W1lo[e] = l;
    } else if (e < 98304) {                // wfc1 [j][k] fp16 split
        int i = e - 32768;
        __half h, l;
        hsplit(wfc1[i], h, l);
        g_WFhi[i] = h; g_WFlo[i] = l;
    } else {                               // w2 [d][c][m] -> [m][d][c] bf16 split
        int i = e - 98304;
        int m = i >> 16, r = i & 65535, d = r >> 8, cc = r & 255;
        __nv_bfloat16 h, l;
        bfsplit(w2[d * 768 + cc * 3 + m], h, l);
        g_W2hi[i] = h; g_W2lo[i] = l;
    }
}

// ============================ kA: precompute Q (bf16x3, unchanged) ============================
#define KA_P    0u
#define KA_AE   131072u
#define KA_STG2 131072u
#define KA_B1   196608
#define SMEM_KA 197632

__global__ __launch_bounds__(512) void kA(
    const float* __restrict__ emb0, const float* __restrict__ emb1,
    const float* __restrict__ emb2, const float* __restrict__ b1)
{
    extern __shared__ char smc[];
    const uint32_t sb = smem_u32(smc);
    float* b1s = (float*)(smc + KA_B1);
    const int tid = threadIdx.x;
    const int lane = tid & 31, w = tid >> 5;
    const int wm = w & 3, wn = w >> 2;
    const int g4 = lane >> 2, tig = lane & 3;

    int b = blockIdx.x, table, gbase, lbase, rows;
    if (b < 3)       { table = 0; int f = b * 128;        lbase = f; gbase = f;           rows = min(128, F0 - f); }
    else if (b < 49) { table = 1; int f = (b - 3) * 128;  lbase = f; gbase = F0 + f;      rows = min(128, F1 - f); }
    else             { table = 2; lbase = 0;              gbase = F0 + F1;                rows = F2; }
    const float* E = (table == 0) ? emb0 : ((table == 1) ? emb1 : emb2);

    if (tid < 256) b1s[tid] = b1[tid];

    {
        #pragma unroll
        for (int it = 0; it < 4; ++it) {
            int idx = tid + it * 512;
            int row = idx >> 4, g = idx & 15;
            int er = lbase + min(row, rows - 1);
            const float4* src = (const float4*)(E + (long long)er * RK + g * 8);
            float4 v0 = src[0], v1 = src[1];
            __nv_bfloat16 h[8], l[8];
            bfsplit(v0.x, h[0], l[0]); bfsplit(v0.y, h[1], l[1]);
            bfsplit(v0.z, h[2], l[2]); bfsplit(v0.w, h[3], l[3]);
            bfsplit(v1.x, h[4], l[4]); bfsplit(v1.y, h[5], l[5]);
            bfsplit(v1.z, h[6], l[6]); bfsplit(v1.w, h[7], l[7]);
            uint32_t off = KA_AE + (uint32_t)((row * 16 + (g ^ (row & 7))) << 4);
            *(uint4*)(smc + off) = make_uint4(pk(h[0], h[1]), pk(h[2], h[3]), pk(h[4], h[5]), pk(h[6], h[7]));
            *(uint4*)(smc + off + 32768) = make_uint4(pk(l[0], l[1]), pk(l[2], l[3]), pk(l[4], l[5]), pk(l[6], l[7]));
        }
    }
    __syncthreads();

    float acc[2][8][4];
    #pragma unroll
    for (int mt = 0; mt < 2; mt++)
        #pragma unroll
        for (int nt = 0; nt < 8; nt++)
            #pragma unroll
            for (int p = 0; p < 4; p++) acc[mt][nt][p] = 0.f;
    gemm_bf16x3<4, 16, false>(sb + KA_AE, sb + KA_P, g_W1hi, g_W1lo, 128, acc, false);

    #pragma unroll
    for (int mt = 0; mt < 2; ++mt) {
        #pragma unroll
        for (int nt = 0; nt < 8; ++nt) {
            int j0 = wn * 64 + nt * 8 + tig * 2;
            float v00 = frelu(acc[mt][nt][0] + b1s[j0]);
            float v01 = frelu(acc[mt][nt][1] + b1s[j0 + 1]);
            float v10 = frelu(acc[mt][nt][2] + b1s[j0]);
            float v11 = frelu(acc[mt][nt][3] + b1s[j0 + 1]);
            __nv_bfloat16 h0, l0, h1, l1;
            int rlo = wm * 32 + mt * 16 + g4;
            int rhi = rlo + 8;
            uint32_t offL = KA_P + (uint32_t)(((rlo * 32 + ((j0 >> 3) ^ (rlo & 7))) << 4) + (j0 & 7) * 2);
            uint32_t offH = KA_P + (uint32_t)(((rhi * 32 + ((j0 >> 3) ^ (rhi & 7))) << 4) + (j0 & 7) * 2);
            bfsplit(v00, h0, l0); bfsplit(v01, h1, l1);
            *(uint32_t*)(smc + offL) = pk(h0, h1);
            *(uint32_t*)(smc + offL + 65536) = pk(l0, l1);
            bfsplit(v10, h0, l0); bfsplit(v11, h1, l1);
            *(uint32_t*)(smc + offH) = pk(h0, h1);
            *(uint32_t*)(smc + offH + 65536) = pk(l0, l1);
        }
    }
    __syncthreads();

    #pragma unroll
    for (int mt = 0; mt < 2; mt++)
        #pragma unroll
        for (int nt = 0; nt < 8; nt++)
            #pragma unroll
            for (int p = 0; p < 4; p++) acc[mt][nt][p] = 0.f;
    gemm_bf16x3<8, 32, false>(sb + KA_P, sb + KA_STG2,
                              g_W2hi + table * 65536, g_W2lo + table * 65536, 256, acc, false);

    #pragma unroll
    for (int mt = 0; mt < 2; ++mt) {
        int rlo = wm * 32 + mt * 16 + g4;
        int rhi = rlo + 8;
        #pragma unroll
        for (int nt = 0; nt < 8; ++nt) {
            int j0 = wn * 64 + nt * 8 + tig * 2;
            if (rlo < rows) {
                float2 v = make_float2(acc[mt][nt][0], acc[mt][nt][1]);
                *(float2*)(g_Q + (gbase + rlo) * CH + j0) = v;
            }
            if (rhi < rows) {
                float2 v = make_float2(acc[mt][nt][2], acc[mt][nt][3]);
                *(float2*)(g_Q + (gbase + rhi) * CH + j0) = v;
            }
        }
    }
}

// ============================ kB: fp16 2-pass, 256 thr / 64 samples, 2 CTA/SM ============================
// A: 64 rows x 512B (fp16, XOR g^(r&7))       = 32768 B
// B: DB x { hi 16384 + lo 16384 } packed 64B rows, swizzle g^((n>>1)&3) = 65536 B
#define KB_A    0u
#define KB_STG  32768u
#define KB_BUF  32768u
#define KB_IDX  98304
#define KB_BF1  99072
#define KB_WF2  100096
#define KB_PS   101120
#define KB_FLAG 102144
#define SMEM_KB 102160

__device__ __forceinline__ void stageBf(uint32_t dbuf, int c, int tid)
{
    #pragma unroll
    for (int it = 0; it < 8; ++it) {
        int idx = tid + it * 256;
        int pl = idx >> 10, rem = idx & 1023;
        int n = rem >> 2, g = rem & 3;
        const __half* src = (pl ? g_WFlo : g_WFhi) + n * 256 + c * 32 + g * 8;
        CP_ASYNC16(dbuf + (uint32_t)(pl * 16384 + n * 64 + ((g ^ ((n >> 1) & 3)) << 4)), src);
    }
    CP_COMMIT();
}

__global__ __launch_bounds__(256, 2) void kB(
    const void* __restrict__ indices,
    const float* __restrict__ b2,
    const float* __restrict__ bfc1,
    const float* __restrict__ wfc2, const float* __restrict__ bfc2,
    float* __restrict__ out, int B)
{
    extern __shared__ char smc[];
    const uint32_t sb = smem_u32(smc);
    int*   idxs = (int*)(smc + KB_IDX);
    float* bf1s = (float*)(smc + KB_BF1);
    float* wf2s = (float*)(smc + KB_WF2);
    float* psum = (float*)(smc + KB_PS);
    int*   flagp = (int*)(smc + KB_FLAG);

    const int tid = threadIdx.x;
    const int lane = tid & 31, w = tid >> 5;
    const int wm = w & 1, wn = w >> 1;
    const int q = lane >> 3, rl = lane & 7;
    const int g4 = lane >> 2, tig = lane & 3;
    const int b0 = blockIdx.x * 64;

    // prestage B chunk 0
    stageBf(sb + KB_STG, 0, tid);

    // index dtype detect (warp 0; dtype-safe read of first 256 words)
    if (w == 0) {
        const uint32_t* rw = (const uint32_t*)indices;
        uint32_t v = rw[lane * 8 + 1] | rw[lane * 8 + 3] | rw[lane * 8 + 5] | rw[lane * 8 + 7];
        int all0 = __all_sync(0xffffffffu, v == 0u);
        if (lane == 0) *flagp = all0;
    }
    if (tid < 256) { bf1s[tid] = bfc1[tid]; wf2s[tid] = wfc2[tid]; }
    __syncthreads();

    const int is64 = *flagp;
    if (tid < 64) {
        long long sg = b0 + tid;
        if (sg > (long long)B - 1) sg = B - 1;
        long long bb = sg * 3;
        int i0, i1, i2;
        if (is64) {
            const long long* ip = (const long long*)indices;
            i0 = (int)ip[bb]; i1 = (int)ip[bb + 1]; i2 = (int)ip[bb + 2];
        } else {
            const int* ip = (const int*)indices;
            i0 = ip[bb]; i1 = ip[bb + 1]; i2 = ip[bb + 2];
        }
        idxs[tid * 3] = i0; idxs[tid * 3 + 1] = i1; idxs[tid * 3 + 2] = i2;
    }
    __syncthreads();

    // gather h2 = relu(Q0[i0]+Q1[i1]+Q2[i2]+b2) -> single fp16 A plane
    {
        const float4* Q0 = (const float4*)g_Q;
        const float4* Q1 = (const float4*)(g_Q + F0 * CH);
        const float4* Q2 = (const float4*)(g_Q + (F0 + F1) * CH);
        const float4* b2v = (const float4*)b2;
        float4 d0 = b2v[2 * lane], d1 = b2v[2 * lane + 1];
        #pragma unroll 2
        for (int it = 0; it < 8; ++it) {
            int s = w * 8 + it;
            int i0 = idxs[s * 3], i1 = idxs[s * 3 + 1], i2 = idxs[s * 3 + 2];
            float4 a0 = Q0[i0 * 64 + 2 * lane], a1 = Q0[i0 * 64 + 2 * lane + 1];
            float4 c0 = Q1[i1 * 64 + 2 * lane], c1 = Q1[i1 * 64 + 2 * lane + 1];
            float4 e0 = Q2[i2 * 64 + 2 * lane], e1 = Q2[i2 * 64 + 2 * lane + 1];
            __half h[8];
            h[0] = __float2half_rn(frelu(a0.x + c0.x + e0.x + d0.x));
            h[1] = __float2half_rn(frelu(a0.y + c0.y + e0.y + d0.y));
            h[2] = __float2half_rn(frelu(a0.z + c0.z + e0.z + d0.z));
            h[3] = __float2half_rn(frelu(a0.w + c0.w + e0.w + d0.w));
            h[4] = __float2half_rn(frelu(a1.x + c1.x + e1.x + d1.x));
            h[5] = __float2half_rn(frelu(a1.y + c1.y + e1.y + d1.y));
            h[6] = __float2half_rn(frelu(a1.z + c1.z + e1.z + d1.z));
            h[7] = __float2half_rn(frelu(a1.w + c1.w + e1.w + d1.w));
            uint32_t off = KB_A + (uint32_t)((s * 32 + (lane ^ (s & 7))) << 4);
            *(uint4*)(smc + off) = make_uint4(pkh(h[0], h[1]), pkh(h[2], h[3]), pkh(h[4], h[5]), pkh(h[6], h[7]));
        }
    }

    // mainloop: 8 K-chunks, DB, fp16 2-pass
    float acc[2][8][4];
    #pragma unroll
    for (int mt = 0; mt < 2; mt++)
        #pragma unroll
        for (int nt = 0; nt < 8; nt++)
            #pragma unroll
            for (int p = 0; p < 4; p++) acc[mt][nt][p] = 0.f;

    const int rA0 = wm * 32 + rl + (q & 1) * 8;
    const int nB0 = wn * 64 + rl + (q >> 1) * 8;
    const int gA  = (q >> 1);
    const int gB  = (q & 1);

    for (int c = 0; c < 8; ++c) {
        if (c + 1 < 8) {
            stageBf(sb + KB_STG + (uint32_t)(((c + 1) & 1) * KB_BUF), c + 1, tid);
            CP_WAIT1();
        } else CP_WAIT0();
        __syncthreads();
        uint32_t cur = sb + KB_STG + (uint32_t)((c & 1) * KB_BUF);

        #pragma unroll
        for (int ks = 0; ks < 2; ++ks) {
            uint32_t a[2][4];
            #pragma unroll
            for (int mt = 0; mt < 2; ++mt) {
                int r = rA0 + mt * 16;
                int g = c * 4 + ks * 2 + gA;
                uint32_t ad = sb + KB_A + (uint32_t)((r * 32 + (g ^ (r & 7))) << 4);
                LDSM_X4(a[mt][0], a[mt][1], a[mt][2], a[mt][3], ad);
            }
            #pragma unroll
            for (int ntp = 0; ntp < 4; ++ntp) {
                int n = nB0 + ntp * 16;
                int kg = ks * 2 + gB;
                uint32_t off = (uint32_t)(n * 64 + ((kg ^ ((n >> 1) & 3)) << 4));
                uint32_t bh[4], bl[4];
                LDSM_X4(bh[0], bh[1], bh[2], bh[3], cur + off);
                LDSM_X4(bl[0], bl[1], bl[2], bl[3], cur + 16384 + off);
                #pragma unroll
                for (int mt = 0; mt < 2; ++mt) {
                    MMA_F16(acc[mt][ntp * 2],     a[mt], bh[0], bh[1]);
                    MMA_F16(acc[mt][ntp * 2],     a[mt], bl[0], bl[1]);
                    MMA_F16(acc[mt][ntp * 2 + 1], a[mt], bh[2], bh[3]);
                    MMA_F16(acc[mt][ntp * 2 + 1], a[mt], bl[2], bl[3]);
                }
            }
        }
        __syncthreads();
    }

    // epilogue: fc1 bias+relu, fc2 dot, quad reduce, combine 4 N-quadrants
    #pragma unroll
    for (int mt = 0; mt < 2; ++mt) {
        float p0 = 0.f, p1 = 0.f;
        #pragma unroll
        for (int nt = 0; nt < 8; ++nt) {
            int j = wn * 64 + nt * 8 + tig * 2;
            float bj0 = bf1s[j], bj1 = bf1s[j + 1];
            float wj0 = wf2s[j], wj1 = wf2s[j + 1];
            p0 += frelu(acc[mt][nt][0] + bj0) * wj0;
            p0 += frelu(acc[mt][nt][1] + bj1) * wj1;
            p1 += frelu(acc[mt][nt][2] + bj0) * wj0;
            p1 += frelu(acc[mt][nt][3] + bj1) * wj1;
        }
        p0 += __shfl_xor_sync(0xffffffffu, p0, 1);
        p0 += __shfl_xor_sync(0xffffffffu, p0, 2);
        p1 += __shfl_xor_sync(0xffffffffu, p1, 1);
        p1 += __shfl_xor_sync(0xffffffffu, p1, 2);
        if (tig == 0) {
            int r = wm * 32 + mt * 16 + g4;
            psum[wn * 64 + r] = p0;
            psum[wn * 64 + r + 8] = p1;
        }
    }
    __syncthreads();
    if (tid < 64) {
        int sg = b0 + tid;
        if (sg < B)
            out[sg] = frelu(psum[tid] + psum[64 + tid] + psum[128 + tid] + psum[192 + tid] + bfc2[0]);
    }
}

// ============================ launch ============================
extern "C" void kernel_launch(void* const* d_in, const int* in_sizes, int n_in,
                              void* d_out, int out_size)
{
    const void*  indices = d_in[0];
    const float* emb0 = (const float*)d_in[1];
    const float* emb1 = (const float*)d_in[2];
    const float* emb2 = (const float*)d_in[3];
    const float* w1   = (const float*)d_in[4];
    const float* b1   = (const float*)d_in[5];
    const float* w2   = (const float*)d_in[6];
    const float* b2   = (const float*)d_in[7];
    const float* wfc1 = (const float*)d_in[8];
    const float* bfc1 = (const float*)d_in[9];
    const float* wfc2 = (const float*)d_in[10];
    const float* bfc2 = (const float*)d_in[11];
    float* out = (float*)d_out;

    int B = in_sizes[0] / 3;

    cudaFuncSetAttribute(kA, cudaFuncAttributeMaxDynamicSharedMemorySize, SMEM_KA);
    cudaFuncSetAttribute(kB, cudaFuncAttributeMaxDynamicSharedMemorySize, SMEM_KB);

    kW<<<1152, 256>>>(w1, wfc1, w2);
    kA<<<50, 512, SMEM_KA>>>(emb0, emb1, emb2, b1);
    int nb = (B + 63) / 64;
    kB<<<nb, 256, SMEM_KB>>>(indices, b2, bfc1, wfc2, bfc2, out, B);
}

// round 14
// speedup vs baseline: 1.6140x; 1.1031x over previous
#include <cuda_runtime.h>
#include <cuda_bf16.h>
#include <cuda_fp16.h>
#include <cstdint>

#define F0 339
#define F1 5825
#define F2 64
#define NROWS 6228
#define RK 128
#define CH 256

__device__ __align__(16) float g_Q[NROWS * CH];
// kA weights (bf16 hi/lo planes)
__device__ __align__(16) __nv_bfloat16 g_W1hi[256 * 128], g_W1lo[256 * 128];         // conv1 [c][r]
__device__ __align__(16) __nv_bfloat16 g_W2hi[3 * 256 * 256], g_W2lo[3 * 256 * 256]; // [m][d][c]
// kB weights (fp16, single plane)
__device__ __align__(16) __half g_WF[256 * 256];                                     // fc1 [j][k]

// ============================ primitives ============================
__device__ __forceinline__ uint32_t smem_u32(const void* p) {
    uint32_t a;
    asm("{ .reg .u64 t; cvta.to.shared.u64 t, %1; cvt.u32.u64 %0, t; }" : "=r"(a) : "l"(p));
    return a;
}
#define LDSM_X4(r0, r1, r2, r3, addr) \
    asm volatile("ldmatrix.sync.aligned.m8n8.x4.shared.b16 {%0,%1,%2,%3}, [%4];" \
        : "=r"(r0), "=r"(r1), "=r"(r2), "=r"(r3) : "r"(addr))
#define MMA_BF16(d, a, b0, b1) \
    asm volatile("mma.sync.aligned.m16n8k16.row.col.f32.bf16.bf16.f32 " \
        "{%0,%1,%2,%3}, {%4,%5,%6,%7}, {%8,%9}, {%0,%1,%2,%3};" \
        : "+f"((d)[0]), "+f"((d)[1]), "+f"((d)[2]), "+f"((d)[3]) \
        : "r"((a)[0]), "r"((a)[1]), "r"((a)[2]), "r"((a)[3]), "r"(b0), "r"(b1))
#define MMA_F16(d, a, b0, b1) \
    asm volatile("mma.sync.aligned.m16n8k16.row.col.f32.f16.f16.f32 " \
        "{%0,%1,%2,%3}, {%4,%5,%6,%7}, {%8,%9}, {%0,%1,%2,%3};" \
        : "+f"((d)[0]), "+f"((d)[1]), "+f"((d)[2]), "+f"((d)[3]) \
        : "r"((a)[0]), "r"((a)[1]), "r"((a)[2]), "r"((a)[3]), "r"(b0), "r"(b1))
#define CP_ASYNC16(dst, src) \
    asm volatile("cp.async.cg.shared.global [%0], [%1], 16;" :: "r"(dst), "l"(src))
#define CP_COMMIT() asm volatile("cp.async.commit_group;" ::: "memory")
#define CP_WAIT0()  asm volatile("cp.async.wait_group 0;" ::: "memory")
#define CP_WAIT1()  asm volatile("cp.async.wait_group 1;" ::: "memory")

__device__ __forceinline__ void bfsplit(float x, __nv_bfloat16& h, __nv_bfloat16& l) {
    h = __float2bfloat16_rn(x);
    l = __float2bfloat16_rn(x - __bfloat162float(h));
}
__device__ __forceinline__ void hsplit(float x, __half& h, __half& l) {
    h = __float2half_rn(x);
    l = __float2half_rn(x - __half2float(h));
}
__device__ __forceinline__ uint32_t pk(__nv_bfloat16 a, __nv_bfloat16 b) {
    __nv_bfloat162 t; t.x = a; t.y = b;
    return *reinterpret_cast<uint32_t*>(&t);
}
__device__ __forceinline__ uint32_t pkh(__half a, __half b) {
    __half2 t; t.x = a; t.y = b;
    return *reinterpret_cast<uint32_t*>(&t);
}
__device__ __forceinline__ float frelu(float x) { return x > 0.f ? x : 0.f; }

// ============================ bf16 B staging (kA, 512 thr, 80B rows) ============================
__device__ __forceinline__ void stageB(uint32_t dbuf,
    const __nv_bfloat16* __restrict__ gBhi, const __nv_bfloat16* __restrict__ gBlo,
    int Ksrc, int c, int tid)
{
    #pragma unroll
    for (int it = 0; it < 4; ++it) {
        int idx = tid + it * 512;
        int pl = idx >> 10, rem = idx & 1023;
        int n = rem >> 2, g = rem & 3;
        const __nv_bfloat16* src = (pl ? gBlo : gBhi) + n * Ksrc + c * 32 + g * 8;
        CP_ASYNC16(dbuf + (uint32_t)(pl * 20480 + n * 80 + g * 16), src);
    }
    CP_COMMIT();
}

// ============================ bf16x3 mainloop (kA; 512 thr, 16 warps, DB) ============================
template<int NCHUNK, int NG>
__device__ __forceinline__ void gemm_bf16x3(
    uint32_t sbA, uint32_t sbB,
    const __nv_bfloat16* __restrict__ gBhi, const __nv_bfloat16* __restrict__ gBlo,
    int Ksrc, float (&acc)[2][8][4])
{
    const int tid = threadIdx.x;
    const int lane = tid & 31;
    const int w = tid >> 5;
    const int wm = w & 3, wn = w >> 2;
    const int q = lane >> 3, rl = lane & 7;
    constexpr uint32_t APLANE = 128u * NG * 16u;

    stageB(sbB, gBhi, gBlo, Ksrc, 0, tid);

    const int rA0 = wm * 32 + rl + (q & 1) * 8;
    const int nB0 = wn * 64 + rl + (q >> 1) * 8;
    const int gA  = (q >> 1);
    const int gB  = (q & 1);

    for (int c = 0; c < NCHUNK; ++c) {
        if (c + 1 < NCHUNK) {
            stageB(sbB + (uint32_t)(((c + 1) & 1) * 40960), gBhi, gBlo, Ksrc, c + 1, tid);
            CP_WAIT1();
        } else CP_WAIT0();
        __syncthreads();
        uint32_t cur = sbB + (uint32_t)((c & 1) * 40960);

        #pragma unroll
        for (int ks = 0; ks < 2; ++ks) {
            uint32_t ah[2][4], al[2][4];
            #pragma unroll
            for (int mt = 0; mt < 2; ++mt) {
                int r = rA0 + mt * 16;
                int g = c * 4 + ks * 2 + gA;
                uint32_t ad = sbA + (uint32_t)((r * NG + (g ^ (r & 7))) << 4);
                LDSM_X4(ah[mt][0], ah[mt][1], ah[mt][2], ah[mt][3], ad);
                LDSM_X4(al[mt][0], al[mt][1], al[mt][2], al[mt][3], ad + APLANE);
            }
            #pragma unroll
            for (int ntp = 0; ntp < 4; ++ntp) {
                int n = nB0 + ntp * 16;
                uint32_t bd = cur + (uint32_t)(n * 80 + (ks * 2 + gB) * 16);
                uint32_t bh[4], bl[4];
                LDSM_X4(bh[0], bh[1], bh[2], bh[3], bd);
                LDSM_X4(bl[0], bl[1], bl[2], bl[3], bd + 20480);
                #pragma unroll
                for (int mt = 0; mt < 2; ++mt) {
                    MMA_BF16(acc[mt][ntp * 2],     ah[mt], bh[0], bh[1]);
                    MMA_BF16(acc[mt][ntp * 2],     al[mt], bh[0], bh[1]);
                    MMA_BF16(acc[mt][ntp * 2],     ah[mt], bl[0], bl[1]);
                    MMA_BF16(acc[mt][ntp * 2 + 1], ah[mt], bh[2], bh[3]);
                    MMA_BF16(acc[mt][ntp * 2 + 1], al[mt], bh[2], bh[3]);
                    MMA_BF16(acc[mt][ntp * 2 + 1], ah[mt], bl[2], bl[3]);
                }
            }
        }
        __syncthreads();
    }
}

// ============================ kW: split weights ============================
__global__ __launch_bounds__(256) void kW(
    const float* __restrict__ w1, const float* __restrict__ wfc1, const float* __restrict__ w2)
{
    int e = blockIdx.x * 256 + threadIdx.x;
    if (e < 32768) {                       // w1 [c][r] bf16 split
        __nv_bfloat16 h, l;
        bfsplit(w1[e], h, l);
        g_W1hi[e] = h; g_W1lo[e] = l;
    } else if (e < 98304) {                // wfc1 [j][k] fp16 single (rn)
        int i = e - 32768;
        g_WF[i] = __float2half_rn(wfc1[i]);
    } else {                               // w2 [d][c][m] -> [m][d][c] bf16 split
        int i = e - 98304;
        int m = i >> 16, r = i & 65535, d = r >> 8, cc = r & 255;
        __nv_bfloat16 h, l;
        bfsplit(w2[d * 768 + cc * 3 + m], h, l);
        g_W2hi[i] = h; g_W2lo[i] = l;
    }
}

// ============================ kA: precompute Q (bf16x3, DB staging) ============================
// smem: [0,131072) P planes (first 81920 doubles as phase1 DB staging);
//       [131072,196608) E planes (phase2 DB staging [131072,212992) overlays);
//       [212992,214016) b1s.
#define KA_P    0u
#define KA_AE   131072u
#define KA_STG2 131072u
#define KA_B1   212992
#define SMEM_KA 214016

__global__ __launch_bounds__(512) void kA(
    const float* __restrict__ emb0, const float* __restrict__ emb1,
    const float* __restrict__ emb2, const float* __restrict__ b1)
{
    extern __shared__ char smc[];
    const uint32_t sb = smem_u32(smc);
    float* b1s = (float*)(smc + KA_B1);
    const int tid = threadIdx.x;
    const int lane = tid & 31, w = tid >> 5;
    const int wm = w & 3, wn = w >> 2;
    const int g4 = lane >> 2, tig = lane & 3;

    int b = blockIdx.x, table, gbase, lbase, rows;
    if (b < 3)       { table = 0; int f = b * 128;        lbase = f; gbase = f;           rows = min(128, F0 - f); }
    else if (b < 49) { table = 1; int f = (b - 3) * 128;  lbase = f; gbase = F0 + f;      rows = min(128, F1 - f); }
    else             { table = 2; lbase = 0;              gbase = F0 + F1;                rows = F2; }
    const float* E = (table == 0) ? emb0 : ((table == 1) ? emb1 : emb2);

    if (tid < 256) b1s[tid] = b1[tid];

    {
        #pragma unroll
        for (int it = 0; it < 4; ++it) {
            int idx = tid + it * 512;
            int row = idx >> 4, g = idx & 15;
            int er = lbase + min(row, rows - 1);
            const float4* src = (const float4*)(E + (long long)er * RK + g * 8);
            float4 v0 = src[0], v1 = src[1];
            __nv_bfloat16 h[8], l[8];
            bfsplit(v0.x, h[0], l[0]); bfsplit(v0.y, h[1], l[1]);
            bfsplit(v0.z, h[2], l[2]); bfsplit(v0.w, h[3], l[3]);
            bfsplit(v1.x, h[4], l[4]); bfsplit(v1.y, h[5], l[5]);
            bfsplit(v1.z, h[6], l[6]); bfsplit(v1.w, h[7], l[7]);
            uint32_t off = KA_AE + (uint32_t)((row * 16 + (g ^ (row & 7))) << 4);
            *(uint4*)(smc + off) = make_uint4(pk(h[0], h[1]), pk(h[2], h[3]), pk(h[4], h[5]), pk(h[6], h[7]));
            *(uint4*)(smc + off + 32768) = make_uint4(pk(l[0], l[1]), pk(l[2], l[3]), pk(l[4], l[5]), pk(l[6], l[7]));
        }
    }
    __syncthreads();

    float acc[2][8][4];
    #pragma unroll
    for (int mt = 0; mt < 2; mt++)
        #pragma unroll
        for (int nt = 0; nt < 8; nt++)
            #pragma unroll
            for (int p = 0; p < 4; p++) acc[mt][nt][p] = 0.f;
    gemm_bf16x3<4, 16>(sb + KA_AE, sb + KA_P, g_W1hi, g_W1lo, 128, acc);

    #pragma unroll
    for (int mt = 0; mt < 2; ++mt) {
        #pragma unroll
        for (int nt = 0; nt < 8; ++nt) {
            int j0 = wn * 64 + nt * 8 + tig * 2;
            float v00 = frelu(acc[mt][nt][0] + b1s[j0]);
            float v01 = frelu(acc[mt][nt][1] + b1s[j0 + 1]);
            float v10 = frelu(acc[mt][nt][2] + b1s[j0]);
            float v11 = frelu(acc[mt][nt][3] + b1s[j0 + 1]);
            __nv_bfloat16 h0, l0, h1, l1;
            int rlo = wm * 32 + mt * 16 + g4;
            int rhi = rlo + 8;
            uint32_t offL = KA_P + (uint32_t)(((rlo * 32 + ((j0 >> 3) ^ (rlo & 7))) << 4) + (j0 & 7) * 2);
            uint32_t offH = KA_P + (uint32_t)(((rhi * 32 + ((j0 >> 3) ^ (rhi & 7))) << 4) + (j0 & 7) * 2);
            bfsplit(v00, h0, l0); bfsplit(v01, h1, l1);
            *(uint32_t*)(smc + offL) = pk(h0, h1);
            *(uint32_t*)(smc + offL + 65536) = pk(l0, l1);
            bfsplit(v10, h0, l0); bfsplit(v11, h1, l1);
            *(uint32_t*)(smc + offH) = pk(h0, h1);
            *(uint32_t*)(smc + offH + 65536) = pk(l0, l1);
        }
    }
    __syncthreads();

    #pragma unroll
    for (int mt = 0; mt < 2; mt++)
        #pragma unroll
        for (int nt = 0; nt < 8; nt++)
            #pragma unroll
            for (int p = 0; p < 4; p++) acc[mt][nt][p] = 0.f;
    gemm_bf16x3<8, 32>(sb + KA_P, sb + KA_STG2,
                       g_W2hi + table * 65536, g_W2lo + table * 65536, 256, acc);

    #pragma unroll
    for (int mt = 0; mt < 2; ++mt) {
        int rlo = wm * 32 + mt * 16 + g4;
        int rhi = rlo + 8;
        #pragma unroll
        for (int nt = 0; nt < 8; ++nt) {
            int j0 = wn * 64 + nt * 8 + tig * 2;
            if (rlo < rows) {
                float2 v = make_float2(acc[mt][nt][0], acc[mt][nt][1]);
                *(float2*)(g_Q + (gbase + rlo) * CH + j0) = v;
            }
            if (rhi < rows) {
                float2 v = make_float2(acc[mt][nt][2], acc[mt][nt][3]);
                *(float2*)(g_Q + (gbase + rhi) * CH + j0) = v;
            }
        }
    }
}

// ============================ kB: A-split fp16 2-pass, 256 thr / 64 samples, 2 CTA/SM ============================
// A: hi 64x512B + lo 64x512B = 65536 B (XOR g^(r&7))
// B: DB x 16384 B single plane, packed 64B rows, swizzle g^((n>>1)&3)
#define KB_A    0u
#define KB_STG  65536u
#define KB_BUF  16384u
#define KB_IDX  98304
#define KB_BF1  99072
#define KB_WF2  100096
#define KB_PS   101120
#define KB_FLAG 102144
#define SMEM_KB 102160

__device__ __forceinline__ void stageBf(uint32_t dbuf, int c, int tid)
{
    #pragma unroll
    for (int it = 0; it < 4; ++it) {
        int idx = tid + it * 256;
        int n = idx >> 2, g = idx & 3;
        const __half* src = g_WF + n * 256 + c * 32 + g * 8;
        CP_ASYNC16(dbuf + (uint32_t)(n * 64 + ((g ^ ((n >> 1) & 3)) << 4)), src);
    }
    CP_COMMIT();
}

__global__ __launch_bounds__(256, 2) void kB(
    const void* __restrict__ indices,
    const float* __restrict__ b2,
    const float* __restrict__ bfc1,
    const float* __restrict__ wfc2, const float* __restrict__ bfc2,
    float* __restrict__ out, int B)
{
    extern __shared__ char smc[];
    const uint32_t sb = smem_u32(smc);
    int*   idxs = (int*)(smc + KB_IDX);
    float* bf1s = (float*)(smc + KB_BF1);
    float* wf2s = (float*)(smc + KB_WF2);
    float* psum = (float*)(smc + KB_PS);
    int*   flagp = (int*)(smc + KB_FLAG);

    const int tid = threadIdx.x;
    const int lane = tid & 31, w = tid >> 5;
    const int wm = w & 1, wn = w >> 1;
    const int q = lane >> 3, rl = lane & 7;
    const int g4 = lane >> 2, tig = lane & 3;
    const int b0 = blockIdx.x * 64;

    // prestage B chunk 0
    stageBf(sb + KB_STG, 0, tid);

    // index dtype detect (warp 0; dtype-safe read of first 256 words)
    if (w == 0) {
        const uint32_t* rw = (const uint32_t*)indices;
        uint32_t v = rw[lane * 8 + 1] | rw[lane * 8 + 3] | rw[lane * 8 + 5] | rw[lane * 8 + 7];
        int all0 = __all_sync(0xffffffffu, v == 0u);
        if (lane == 0) *flagp = all0;
    }
    if (tid < 256) { bf1s[tid] = bfc1[tid]; wf2s[tid] = wfc2[tid]; }
    __syncthreads();

    const int is64 = *flagp;
    if (tid < 64) {
        long long sg = b0 + tid;
        if (sg > (long long)B - 1) sg = B - 1;
        long long bb = sg * 3;
        int i0, i1, i2;
        if (is64) {
            const long long* ip = (const long long*)indices;
            i0 = (int)ip[bb]; i1 = (int)ip[bb + 1]; i2 = (int)ip[bb + 2];
        } else {
            const int* ip = (const int*)indices;
            i0 = ip[bb]; i1 = ip[bb + 1]; i2 = ip[bb + 2];
        }
        idxs[tid * 3] = i0; idxs[tid * 3 + 1] = i1; idxs[tid * 3 + 2] = i2;
    }
    __syncthreads();

    // gather h2 = relu(Q0[i0]+Q1[i1]+Q2[i2]+b2) -> fp16 hi/lo A planes
    {
        const float4* Q0 = (const float4*)g_Q;
        const float4* Q1 = (const float4*)(g_Q + F0 * CH);
        const float4* Q2 = (const float4*)(g_Q + (F0 + F1) * CH);
        const float4* b2v = (const float4*)b2;
        float4 d0 = b2v[2 * lane], d1 = b2v[2 * lane + 1];
        #pragma unroll 2
        for (int it = 0; it < 8; ++it) {
            int s = w * 8 + it;
            int i0 = idxs[s * 3], i1 = idxs[s * 3 + 1], i2 = idxs[s * 3 + 2];
            float4 a0 = Q0[i0 * 64 + 2 * lane], a1 = Q0[i0 * 64 + 2 * lane + 1];
            float4 c0 = Q1[i1 * 64 + 2 * lane], c1 = Q1[i1 * 64 + 2 * lane + 1];
            float4 e0 = Q2[i2 * 64 + 2 * lane], e1 = Q2[i2 * 64 + 2 * lane + 1];
            float f[8];
            f[0] = frelu(a0.x + c0.x + e0.x + d0.x);
            f[1] = frelu(a0.y + c0.y + e0.y + d0.y);
            f[2] = frelu(a0.z + c0.z + e0.z + d0.z);
            f[3] = frelu(a0.w + c0.w + e0.w + d0.w);
            f[4] = frelu(a1.x + c1.x + e1.x + d1.x);
            f[5] = frelu(a1.y + c1.y + e1.y + d1.y);
            f[6] = frelu(a1.z + c1.z + e1.z + d1.z);
            f[7] = frelu(a1.w + c1.w + e1.w + d1.w);
            __half h[8], l[8];
            #pragma unroll
            for (int i = 0; i < 8; ++i) hsplit(f[i], h[i], l[i]);
            uint32_t off = KB_A + (uint32_t)((s * 32 + (lane ^ (s & 7))) << 4);
            *(uint4*)(smc + off) = make_uint4(pkh(h[0], h[1]), pkh(h[2], h[3]), pkh(h[4], h[5]), pkh(h[6], h[7]));
            *(uint4*)(smc + off + 32768) = make_uint4(pkh(l[0], l[1]), pkh(l[2], l[3]), pkh(l[4], l[5]), pkh(l[6], l[7]));
        }
    }

    // mainloop: 8 K-chunks, DB, A hi/lo x B single
    float acc[2][8][4];
    #pragma unroll
    for (int mt = 0; mt < 2; mt++)
        #pragma unroll
        for (int nt = 0; nt < 8; nt++)
            #pragma unroll
            for (int p = 0; p < 4; p++) acc[mt][nt][p] = 0.f;

    const int rA0 = wm * 32 + rl + (q & 1) * 8;
    const int nB0 = wn * 64 + rl + (q >> 1) * 8;
    const int gA  = (q >> 1);
    const int gB  = (q & 1);

    for (int c = 0; c < 8; ++c) {
        if (c + 1 < 8) {
            stageBf(sb + KB_STG + (uint32_t)(((c + 1) & 1) * KB_BUF), c + 1, tid);
            CP_WAIT1();
        } else CP_WAIT0();
        __syncthreads();
        uint32_t cur = sb + KB_STG + (uint32_t)((c & 1) * KB_BUF);

        #pragma unroll
        for (int ks = 0; ks < 2; ++ks) {
            uint32_t ah[2][4], al[2][4];
            #pragma unroll
            for (int mt = 0; mt < 2; ++mt) {
                int r = rA0 + mt * 16;
                int g = c * 4 + ks * 2 + gA;
                uint32_t ad = sb + KB_A + (uint32_t)((r * 32 + (g ^ (r & 7))) << 4);
                LDSM_X4(ah[mt][0], ah[mt][1], ah[mt][2], ah[mt][3], ad);
                LDSM_X4(al[mt][0], al[mt][1], al[mt][2], al[mt][3], ad + 32768);
            }
            #pragma unroll
            for (int ntp = 0; ntp < 4; ++ntp) {
                int n = nB0 + ntp * 16;
                int kg = ks * 2 + gB;
                uint32_t off = (uint32_t)(n * 64 + ((kg ^ ((n >> 1) & 3)) << 4));
                uint32_t bf[4];
                LDSM_X4(bf[0], bf[1], bf[2], bf[3], cur + off);
                #pragma unroll
                for (int mt = 0; mt < 2; ++mt) {
                    MMA_F16(acc[mt][ntp * 2],     ah[mt], bf[0], bf[1]);
                    MMA_F16(acc[mt][ntp * 2],     al[mt], bf[0], bf[1]);
                    MMA_F16(acc[mt][ntp * 2 + 1], ah[mt], bf[2], bf[3]);
                    MMA_F16(acc[mt][ntp * 2 + 1], al[mt], bf[2], bf[3]);
                }
            }
        }
        __syncthreads();
    }

    // epilogue: fc1 bias+relu, fc2 dot, quad reduce, combine 4 N-quadrants
    #pragma unroll
    for (int mt = 0; mt < 2; ++mt) {
        float p0 = 0.f, p1 = 0.f;
        #pragma unroll
        for (int nt = 0; nt < 8; ++nt) {
            int j = wn * 64 + nt * 8 + tig * 2;
            float bj0 = bf1s[j], bj1 = bf1s[j + 1];
            float wj0 = wf2s[j], wj1 = wf2s[j + 1];
            p0 += frelu(acc[mt][nt][0] + bj0) * wj0;
            p0 += frelu(acc[mt][nt][1] + bj1) * wj1;
            p1 += frelu(acc[mt][nt][2] + bj0) * wj0;
            p1 += frelu(acc[mt][nt][3] + bj1) * wj1;
        }
        p0 += __shfl_xor_sync(0xffffffffu, p0, 1);
        p0 += __shfl_xor_sync(0xffffffffu, p0, 2);
        p1 += __shfl_xor_sync(0xffffffffu, p1, 1);
        p1 += __shfl_xor_sync(0xffffffffu, p1, 2);
        if (tig == 0) {
            int r = wm * 32 + mt * 16 + g4;
            psum[wn * 64 + r] = p0;
            psum[wn * 64 + r + 8] = p1;
        }
    }
    __syncthreads();
    if (tid < 64) {
        int sg = b0 + tid;
        if (sg < B)
            out[sg] = frelu(psum[tid] + psum[64 + tid] + psum[128 + tid] + psum[192 + tid] + bfc2[0]);
    }
}

// ============================ launch ============================
extern "C" void kernel_launch(void* const* d_in, const int* in_sizes, int n_in,
                              void* d_out, int out_size)
{
    const void*  indices = d_in[0];
    const float* emb0 = (const float*)d_in[1];
    const float* emb1 = (const float*)d_in[2];
    const float* emb2 = (const float*)d_in[3];
    const float* w1   = (const float*)d_in[4];
    const float* b1   = (const float*)d_in[5];
    const float* w2   = (const float*)d_in[6];
    const float* b2   = (const float*)d_in[7];
    const float* wfc1 = (const float*)d_in[8];
    const float* bfc1 = (const float*)d_in[9];
    const float* wfc2 = (const float*)d_in[10];
    const float* bfc2 = (const float*)d_in[11];
    float* out = (float*)d_out;

    int B = in_sizes[0] / 3;

    cudaFuncSetAttribute(kA, cudaFuncAttributeMaxDynamicSharedMemorySize, SMEM_KA);
    cudaFuncSetAttribute(kB, cudaFuncAttributeMaxDynamicSharedMemorySize, SMEM_KB);

    kW<<<1152, 256>>>(w1, wfc1, w2);
    kA<<<50, 512, SMEM_KA>>>(emb0, emb1, emb2, b1);
    int nb = (B + 63) / 64;
    kB<<<nb, 256, SMEM_KB>>>(indices, b2, bfc1, wfc2, bfc2, out, B);
}